// round 11
// baseline (speedup 1.0000x reference)
#include <cuda_runtime.h>
#include <cuda_fp16.h>
#include <cstdint>

#define DIM    2048
#define NROWS  16384   // 4 * 4096
#define LNCHUNK 4096   // ln rows fused per prep stage

// GEMM tiling (single fp16 pass, K = 2048) — R9-proven config
#define BM 256
#define BN 128
#define BK 64
#define NKT 32
#define GTHREADS 512
#define ABYTES (BM * BK * 2)       // 32768
#define BBYTES (BN * BK * 2)       // 16384
#define STAGE  (ABYTES + BBYTES)   // 49152
#define NSTAGE 4
#define GEMM_SMEM (NSTAGE * STAGE) // 196608

// ---------------------------------------------------------------------------
// Scratch (static __device__ globals — allocation-free per harness rules)
// ---------------------------------------------------------------------------
__device__ float   g_wpart[256];
__device__ float   g_B1[DIM * DIM];            // fwht_rows(ternary(W))   [o][d]
__device__ float   g_B1T[DIM * DIM];           // transpose               [d][o]
__device__ __half  g_BqT[DIM * DIM];           // fwht rows of B1T (fp16) [d][o]
__device__ __half  g_Bq[DIM * DIM];            // final B operand         [o][d]
__device__ __half  g_Xq[(size_t)NROWS * DIM];  // x_int exact in fp16
__device__ float   g_rowscale[NROWS];          // x_scale / 7

// ---------------------------------------------------------------------------
// Helpers
// ---------------------------------------------------------------------------
static __device__ __forceinline__ uint32_t smem_u32(const void* p) {
    uint32_t a;
    asm("{ .reg .u64 t; cvta.to.shared.u64 t, %1; cvt.u32.u64 %0, t; }"
        : "=r"(a) : "l"(p));
    return a;
}

static __device__ __forceinline__ void cp_async16(uint32_t dst, const void* src) {
    asm volatile("cp.async.cg.shared.global [%0], [%1], 16;" :: "r"(dst), "l"(src));
}

static __device__ __forceinline__ void ldmatrix_x4(uint32_t* r, uint32_t addr) {
    asm volatile("ldmatrix.sync.aligned.m8n8.x4.shared.b16 {%0,%1,%2,%3}, [%4];"
                 : "=r"(r[0]), "=r"(r[1]), "=r"(r[2]), "=r"(r[3]) : "r"(addr));
}

static __device__ __forceinline__ void ldmatrix_x2(uint32_t* r, uint32_t addr) {
    asm volatile("ldmatrix.sync.aligned.m8n8.x2.shared.b16 {%0,%1}, [%2];"
                 : "=r"(r[0]), "=r"(r[1]) : "r"(addr));
}

static __device__ __forceinline__ void mma_f16(float* c, const uint32_t* a, const uint32_t* b) {
    asm volatile(
        "mma.sync.aligned.m16n8k16.row.col.f32.f16.f16.f32 "
        "{%0,%1,%2,%3}, {%4,%5,%6,%7}, {%8,%9}, {%0,%1,%2,%3};"
        : "+f"(c[0]), "+f"(c[1]), "+f"(c[2]), "+f"(c[3])
        : "r"(a[0]), "r"(a[1]), "r"(a[2]), "r"(a[3]), "r"(b[0]), "r"(b[1]));
}

// ---------------------------------------------------------------------------
// Block reductions (deterministic fixed-order trees)
// ---------------------------------------------------------------------------
static __device__ __forceinline__ float block_sum256(float v, float* red) {
    #pragma unroll
    for (int o = 16; o; o >>= 1) v += __shfl_xor_sync(0xFFFFFFFFu, v, o);
    if ((threadIdx.x & 31) == 0) red[threadIdx.x >> 5] = v;
    __syncthreads();
    float t = red[0];
    #pragma unroll
    for (int w = 1; w < 8; w++) t += red[w];
    __syncthreads();
    return t;
}

static __device__ __forceinline__ float block_max256(float v, float* red) {
    #pragma unroll
    for (int o = 16; o; o >>= 1) v = fmaxf(v, __shfl_xor_sync(0xFFFFFFFFu, v, o));
    if ((threadIdx.x & 31) == 0) red[threadIdx.x >> 5] = v;
    __syncthreads();
    float t = red[0];
    #pragma unroll
    for (int w = 1; w < 8; w++) t = fmaxf(t, red[w]);
    __syncthreads();
    return t;
}

// ---------------------------------------------------------------------------
// LayerNorm + 4-bit quant for one row (callable from any 256-thread block)
// ---------------------------------------------------------------------------
static __device__ void ln_block(int row, const float* __restrict__ x,
                                const float* __restrict__ gamma,
                                const float* __restrict__ beta) {
    __shared__ float red[8];
    const float* xr = x + (size_t)row * DIM;
    float v[8];
    float s = 0.f;
    #pragma unroll
    for (int t = 0; t < 8; t++) { v[t] = xr[threadIdx.x + t * 256]; s += v[t]; }
    s = block_sum256(s, red);
    const float mu = s * (1.f / (float)DIM);
    float sq = 0.f;
    #pragma unroll
    for (int t = 0; t < 8; t++) { float c = v[t] - mu; sq += c * c; }
    sq = block_sum256(sq, red);
    const float rstd = rsqrtf(sq * (1.f / (float)DIM) + 1e-5f);
    float mx = 0.f;
    #pragma unroll
    for (int t = 0; t < 8; t++) {
        int j = threadIdx.x + t * 256;
        float xl = (v[t] - mu) * rstd * gamma[j] + beta[j];
        v[t] = xl;
        mx = fmaxf(mx, fabsf(xl));
    }
    mx = block_max256(mx, red);
    const float xs = fmaxf(mx, 1e-6f);
    #pragma unroll
    for (int t = 0; t < 8; t++) {
        float r = rintf(v[t] * 7.0f / xs);   // round-half-even matches jnp.round
        r = fminf(fmaxf(r, -7.f), 7.f);
        g_Xq[(size_t)row * DIM + threadIdx.x + t * 256] = __float2half_rn(r);
    }
    if (threadIdx.x == 0) g_rowscale[row] = xs * (1.f / 7.f);
}

// ---------------------------------------------------------------------------
// K0: partial sums of |W| -> g_wpart (reduced redundantly inside stage 1)
// ---------------------------------------------------------------------------
__global__ void k_wabs_part(const float* __restrict__ W) {
    float s = 0.f;
    for (int i = blockIdx.x * 256 + threadIdx.x; i < DIM * DIM; i += 256 * 256)
        s += fabsf(W[i]);
    #pragma unroll
    for (int o = 16; o; o >>= 1) s += __shfl_xor_sync(0xFFFFFFFFu, s, o);
    __shared__ float red[8];
    if ((threadIdx.x & 31) == 0) red[threadIdx.x >> 5] = s;
    __syncthreads();
    if (threadIdx.x == 0) {
        float t = 0.f;
        #pragma unroll
        for (int w = 0; w < 8; w++) t += red[w];
        g_wpart[blockIdx.x] = t;
    }
}

// ---------------------------------------------------------------------------
// Register/shuffle FWHT over one 2048-row, 256 threads x 8 elements.
// ---------------------------------------------------------------------------
#define BFLY(a, b) { float _x = (a), _y = (b); (a) = _x + _y; (b) = _x - _y; }

static __device__ __forceinline__ void fwht_reg8(float* v) {
    BFLY(v[0], v[1]); BFLY(v[2], v[3]); BFLY(v[4], v[5]); BFLY(v[6], v[7]);
    BFLY(v[0], v[2]); BFLY(v[1], v[3]); BFLY(v[4], v[6]); BFLY(v[5], v[7]);
    BFLY(v[0], v[4]); BFLY(v[1], v[5]); BFLY(v[2], v[6]); BFLY(v[3], v[7]);
}

static __device__ __forceinline__ void fwht_shfl5(float* v, int lane) {
    #pragma unroll
    for (int b = 1; b <= 16; b <<= 1) {
        #pragma unroll
        for (int j = 0; j < 8; j++) {
            float p = __shfl_xor_sync(0xFFFFFFFFu, v[j], b);
            v[j] = (lane & b) ? (p - v[j]) : (v[j] + p);
        }
    }
}

// ---------------------------------------------------------------------------
// Stage 1: blocks [0,2048) ternarize+FWHT W rows; blocks [2048,6144) ln chunk 0
// ---------------------------------------------------------------------------
__global__ void __launch_bounds__(256)
k_wq_fwht_ln(const float* __restrict__ W, const float* __restrict__ x,
             const float* __restrict__ gamma, const float* __restrict__ beta) {
    if (blockIdx.x >= DIM) {
        ln_block(blockIdx.x - DIM, x, gamma, beta);
        return;
    }
    __shared__ float s[DIM];
    __shared__ float red[8];
    const int o = blockIdx.x, t = threadIdx.x, lane = t & 31, w = t >> 5;

    // inline wscale reduction (identical order to old k_wabs_fin)
    float ps = g_wpart[t];
    ps = block_sum256(ps, red);
    const float ws = fmaxf(ps / (float)(DIM * DIM), 1e-6f);
    const float th = 0.5f * ws;

    const float* wr = W + (size_t)o * DIM;
    float v[8];
    #pragma unroll
    for (int j = 0; j < 8; j++) {
        float xw = wr[j * 256 + t];
        v[j] = (xw > th) ? ws : ((xw < -th) ? -ws : 0.f);
    }
    fwht_reg8(v);            // bits 8,9,10
    fwht_shfl5(v, lane);     // bits 0..4
    #pragma unroll
    for (int j = 0; j < 8; j++) s[j * 256 + t] = v[j];
    __syncthreads();
    #pragma unroll
    for (int j = 0; j < 8; j++) v[j] = s[w * 256 + j * 32 + lane];
    fwht_reg8(v);            // bits 5,6,7
    float* orow = g_B1 + (size_t)o * DIM;
    #pragma unroll
    for (int j = 0; j < 8; j++) orow[w * 256 + j * 32 + lane] = v[j];
}

// ---------------------------------------------------------------------------
// Stage 2: blocks [0,4096) f32 transpose g_B1 -> g_B1T; [4096,8192) ln chunk 1
// ---------------------------------------------------------------------------
__global__ void __launch_bounds__(256)
k_tr32_ln(const float* __restrict__ x, const float* __restrict__ gamma,
          const float* __restrict__ beta) {
    if (blockIdx.x >= 4096) {
        ln_block(LNCHUNK + (blockIdx.x - 4096), x, gamma, beta);
        return;
    }
    __shared__ float t[32][33];
    const int tx = threadIdx.x & 31, ty = threadIdx.x >> 5;
    const int gx = blockIdx.x & 63, gy = blockIdx.x >> 6;
    const int xc = gx * 32 + tx, y0 = gy * 32 + ty;
    #pragma unroll
    for (int j = 0; j < 4; j++)
        t[ty + j * 8][tx] = g_B1[(size_t)(y0 + j * 8) * DIM + xc];
    __syncthreads();
    const int x2 = gy * 32 + tx, y2 = gx * 32 + ty;
    #pragma unroll
    for (int j = 0; j < 4; j++)
        g_B1T[(size_t)(y2 + j * 8) * DIM + x2] = t[tx][ty + j * 8];
}

// ---------------------------------------------------------------------------
// Stage 3: blocks [0,2048) FWHT rows of g_B1T -> fp16 g_BqT; [2048,6144) ln c2
// ---------------------------------------------------------------------------
__global__ void __launch_bounds__(256)
k_fwht_rows_ln(const float* __restrict__ x, const float* __restrict__ gamma,
               const float* __restrict__ beta) {
    if (blockIdx.x >= DIM) {
        ln_block(2 * LNCHUNK + (blockIdx.x - DIM), x, gamma, beta);
        return;
    }
    __shared__ float s[DIM];
    const int d = blockIdx.x, t = threadIdx.x, lane = t & 31, w = t >> 5;
    const float* ir = g_B1T + (size_t)d * DIM;
    float v[8];
    #pragma unroll
    for (int j = 0; j < 8; j++) v[j] = ir[j * 256 + t];
    fwht_reg8(v);
    fwht_shfl5(v, lane);
    #pragma unroll
    for (int j = 0; j < 8; j++) s[j * 256 + t] = v[j];
    __syncthreads();
    #pragma unroll
    for (int j = 0; j < 8; j++) v[j] = s[w * 256 + j * 32 + lane];
    fwht_reg8(v);
    __half* orow = g_BqT + (size_t)d * DIM;
    #pragma unroll
    for (int j = 0; j < 8; j++)
        orow[w * 256 + j * 32 + lane] = __float2half_rn(v[j]);
}

// ---------------------------------------------------------------------------
// Stage 4: blocks [0,4096) f16 transpose g_BqT -> g_Bq; [4096,8192) ln chunk 3
// ---------------------------------------------------------------------------
__global__ void __launch_bounds__(256)
k_tr16_ln(const float* __restrict__ x, const float* __restrict__ gamma,
          const float* __restrict__ beta) {
    if (blockIdx.x >= 4096) {
        ln_block(3 * LNCHUNK + (blockIdx.x - 4096), x, gamma, beta);
        return;
    }
    __shared__ __half t[32][34];
    const int tx = threadIdx.x & 31, ty = threadIdx.x >> 5;
    const int gx = blockIdx.x & 63, gy = blockIdx.x >> 6;
    const int xc = gx * 32 + tx, y0 = gy * 32 + ty;
    #pragma unroll
    for (int j = 0; j < 4; j++)
        t[ty + j * 8][tx] = g_BqT[(size_t)(y0 + j * 8) * DIM + xc];
    __syncthreads();
    const int x2 = gy * 32 + tx, y2 = gx * 32 + ty;
    #pragma unroll
    for (int j = 0; j < 4; j++)
        g_Bq[(size_t)(y2 + j * 8) * DIM + x2] = t[tx][ty + j * 8];
}

// ---------------------------------------------------------------------------
// K4: GEMM via mma.sync (HMMA fp16, fp32 accum) — R9-proven config.
//   CTA 256x128, BK=64, 512 threads, 16 warps 4x4, warp tile 64x32.
//   4-stage cp.async ring + supertile rasterization.
// ---------------------------------------------------------------------------
static __device__ __forceinline__ void load_A(uint32_t base, const __half* gA,
                                              int ksrc, int tid) {
    #pragma unroll
    for (int i = 0; i < 4; i++) {
        int idx = tid + i * GTHREADS;
        int r = idx >> 3, c = idx & 7;
        uint32_t so = (uint32_t)(r * 128 + ((c ^ (r & 7)) << 4));
        cp_async16(base + so, (const char*)(gA + (size_t)r * DIM + ksrc) + c * 16);
    }
}

static __device__ __forceinline__ void load_B(uint32_t base, const __half* gB,
                                              int ksrc, int tid) {
    #pragma unroll
    for (int i = 0; i < 2; i++) {
        int idx = tid + i * GTHREADS;
        int r = idx >> 3, c = idx & 7;
        uint32_t so = (uint32_t)(r * 128 + ((c ^ (r & 7)) << 4));
        cp_async16(base + so, (const char*)(gB + (size_t)r * DIM + ksrc) + c * 16);
    }
}

__global__ void __launch_bounds__(GTHREADS, 1)
k_gemm(float* __restrict__ out) {
    extern __shared__ char smem[];
    const uint32_t sb = smem_u32(smem);
    const int tid  = threadIdx.x;
    const int lane = tid & 31;
    const int wid  = tid >> 5;
    const int wm   = (wid >> 2) * 64;     // warp m-offset in CTA tile
    const int wn   = (wid & 3) * 32;      // warp n-offset

    // Supertile rasterization: 8 mt x 16 nt = 128-CTA supertiles.
    const int bid = blockIdx.x;           // 0..1023 (64 mt x 16 nt)
    const int st  = bid >> 7;
    const int r7  = bid & 127;
    const int mt  = st * 8 + (r7 & 7);
    const int nt  = r7 >> 3;
    const int mBase = mt * BM;
    const int nBase = nt * BN;

    const __half* gA = g_Xq + (size_t)mBase * DIM;
    const __half* gB = g_Bq + (size_t)nBase * DIM;

    float acc[4][4][4];
    #pragma unroll
    for (int i = 0; i < 4; i++)
        #pragma unroll
        for (int j = 0; j < 4; j++)
            #pragma unroll
            for (int q = 0; q < 4; q++) acc[i][j][q] = 0.f;

    // Prologue: stages 0,1,2 <- kt 0,1,2
    #pragma unroll
    for (int p = 0; p < NSTAGE - 1; p++) {
        load_A(sb + p * STAGE, gA, p * BK, tid);
        load_B(sb + p * STAGE + ABYTES, gB, p * BK, tid);
        asm volatile("cp.async.commit_group;" ::: "memory");
    }

    int stage = 0;
    for (int kt = 0; kt < NKT; kt++) {
        if (kt < NKT - 2)       asm volatile("cp.async.wait_group 2;" ::: "memory");
        else if (kt == NKT - 2) asm volatile("cp.async.wait_group 1;" ::: "memory");
        else                    asm volatile("cp.async.wait_group 0;" ::: "memory");
        __syncthreads();

        const uint32_t aB = sb + stage * STAGE;
        const uint32_t bB = aB + ABYTES;

        #pragma unroll
        for (int ks = 0; ks < 4; ks++) {
            uint32_t af[4][4], bf[4][2];
            #pragma unroll
            for (int im = 0; im < 4; im++) {
                int r = wm + im * 16 + (lane & 15);
                uint32_t chunk = (uint32_t)((ks * 2 + (lane >> 4)) ^ (r & 7));
                ldmatrix_x4(af[im], aB + r * 128 + (chunk << 4));
            }
            #pragma unroll
            for (int in = 0; in < 4; in++) {
                int r = wn + in * 8 + (lane & 7);
                uint32_t chunk = (uint32_t)((ks * 2 + ((lane >> 3) & 1)) ^ (r & 7));
                ldmatrix_x2(bf[in], bB + r * 128 + (chunk << 4));
            }
            #pragma unroll
            for (int im = 0; im < 4; im++)
                #pragma unroll
                for (int in = 0; in < 4; in++)
                    mma_f16(acc[im][in], af[im], bf[in]);
        }

        if (kt + NSTAGE - 1 < NKT) {
            const int k2 = kt + NSTAGE - 1;
            const int st2 = (stage + NSTAGE - 1) & (NSTAGE - 1);
            const uint32_t nb = sb + st2 * STAGE;
            load_A(nb, gA, k2 * BK, tid);
            load_B(nb + ABYTES, gB, k2 * BK, tid);
            asm volatile("cp.async.commit_group;" ::: "memory");
        }
        stage = (stage + 1) & (NSTAGE - 1);
    }

    // Epilogue: d frag -> (row = lane/4 [+8], col = 2*(lane%4) [+1])
    #pragma unroll
    for (int im = 0; im < 4; im++) {
        const int r0 = mBase + wm + im * 16 + (lane >> 2);
        const int r1 = r0 + 8;
        const float s0 = g_rowscale[r0];
        const float s1 = g_rowscale[r1];
        #pragma unroll
        for (int in = 0; in < 4; in++) {
            const int col = nBase + wn + in * 8 + (lane & 3) * 2;
            float2 v0 = make_float2(acc[im][in][0] * s0, acc[im][in][1] * s0);
            float2 v1 = make_float2(acc[im][in][2] * s1, acc[im][in][3] * s1);
            *reinterpret_cast<float2*>(out + (size_t)r0 * DIM + col) = v0;
            *reinterpret_cast<float2*>(out + (size_t)r1 * DIM + col) = v1;
        }
    }
}

// ---------------------------------------------------------------------------
// Launcher
// ---------------------------------------------------------------------------
extern "C" void kernel_launch(void* const* d_in, const int* in_sizes, int n_in,
                              void* d_out, int out_size) {
    const float* x     = (const float*)d_in[0];
    const float* W     = (const float*)d_in[1];
    const float* gamma = (const float*)d_in[2];
    const float* beta  = (const float*)d_in[3];
    float* out = (float*)d_out;

    cudaFuncSetAttribute(k_gemm, cudaFuncAttributeMaxDynamicSharedMemorySize,
                         GEMM_SMEM);

    k_wabs_part<<<256, 256>>>(W);
    k_wq_fwht_ln<<<DIM + LNCHUNK, 256>>>(W, x, gamma, beta);
    k_tr32_ln<<<4096 + LNCHUNK, 256>>>(x, gamma, beta);
    k_fwht_rows_ln<<<DIM + LNCHUNK, 256>>>(x, gamma, beta);
    k_tr16_ln<<<4096 + LNCHUNK, 256>>>(x, gamma, beta);

    k_gemm<<<(NROWS / BM) * (DIM / BN), GTHREADS, GEMM_SMEM>>>(out);
}

// round 12
// speedup vs baseline: 1.0507x; 1.0507x over previous
#include <cuda_runtime.h>
#include <cuda_fp16.h>
#include <cstdint>

#define DIM    2048
#define NROWS  16384   // 4 * 4096

// GEMM tiling (single fp16 pass, K = 2048) — 2 CTA/SM config
#define BM 128
#define BN 128
#define BK 64
#define NKT 32
#define GTHREADS 256               // 8 warps, 2x4 warp grid, warp tile 64x32
#define ABYTES (BM * BK * 2)       // 16384
#define BBYTES (BN * BK * 2)       // 16384
#define STAGE  (ABYTES + BBYTES)   // 32768
#define NSTAGE 3
#define GEMM_SMEM (NSTAGE * STAGE) // 98304  -> 2 CTAs/SM

// ---------------------------------------------------------------------------
// Scratch (static __device__ globals — allocation-free per harness rules)
// ---------------------------------------------------------------------------
__device__ float   g_wpart[256];
__device__ float   g_wscale;
__device__ float   g_B1[DIM * DIM];            // fwht_rows(ternary(W))   [o][d]
__device__ float   g_B1T[DIM * DIM];           // transpose               [d][o]
__device__ __half  g_BqT[DIM * DIM];           // fwht rows of B1T (fp16) [d][o]
__device__ __half  g_Bq[DIM * DIM];            // final B operand         [o][d]
__device__ __half  g_Xq[(size_t)NROWS * DIM];  // x_int exact in fp16
__device__ float   g_rowscale[NROWS];          // x_scale / 7

// ---------------------------------------------------------------------------
// Helpers
// ---------------------------------------------------------------------------
static __device__ __forceinline__ uint32_t smem_u32(const void* p) {
    uint32_t a;
    asm("{ .reg .u64 t; cvta.to.shared.u64 t, %1; cvt.u32.u64 %0, t; }"
        : "=r"(a) : "l"(p));
    return a;
}

static __device__ __forceinline__ void cp_async16(uint32_t dst, const void* src) {
    asm volatile("cp.async.cg.shared.global [%0], [%1], 16;" :: "r"(dst), "l"(src));
}

static __device__ __forceinline__ void ldmatrix_x4(uint32_t* r, uint32_t addr) {
    asm volatile("ldmatrix.sync.aligned.m8n8.x4.shared.b16 {%0,%1,%2,%3}, [%4];"
                 : "=r"(r[0]), "=r"(r[1]), "=r"(r[2]), "=r"(r[3]) : "r"(addr));
}

static __device__ __forceinline__ void ldmatrix_x2(uint32_t* r, uint32_t addr) {
    asm volatile("ldmatrix.sync.aligned.m8n8.x2.shared.b16 {%0,%1}, [%2];"
                 : "=r"(r[0]), "=r"(r[1]) : "r"(addr));
}

static __device__ __forceinline__ void mma_f16(float* c, const uint32_t* a, const uint32_t* b) {
    asm volatile(
        "mma.sync.aligned.m16n8k16.row.col.f32.f16.f16.f32 "
        "{%0,%1,%2,%3}, {%4,%5,%6,%7}, {%8,%9}, {%0,%1,%2,%3};"
        : "+f"(c[0]), "+f"(c[1]), "+f"(c[2]), "+f"(c[3])
        : "r"(a[0]), "r"(a[1]), "r"(a[2]), "r"(a[3]), "r"(b[0]), "r"(b[1]));
}

// ---------------------------------------------------------------------------
// Block reductions (deterministic fixed-order trees)
// ---------------------------------------------------------------------------
static __device__ __forceinline__ float block_sum256(float v, float* red) {
    #pragma unroll
    for (int o = 16; o; o >>= 1) v += __shfl_xor_sync(0xFFFFFFFFu, v, o);
    if ((threadIdx.x & 31) == 0) red[threadIdx.x >> 5] = v;
    __syncthreads();
    float t = red[0];
    #pragma unroll
    for (int w = 1; w < 8; w++) t += red[w];
    __syncthreads();
    return t;
}

static __device__ __forceinline__ float block_max256(float v, float* red) {
    #pragma unroll
    for (int o = 16; o; o >>= 1) v = fmaxf(v, __shfl_xor_sync(0xFFFFFFFFu, v, o));
    if ((threadIdx.x & 31) == 0) red[threadIdx.x >> 5] = v;
    __syncthreads();
    float t = red[0];
    #pragma unroll
    for (int w = 1; w < 8; w++) t = fmaxf(t, red[w]);
    __syncthreads();
    return t;
}

// ---------------------------------------------------------------------------
// K0: mean(|W|) -> g_wscale
// ---------------------------------------------------------------------------
__global__ void k_wabs_part(const float* __restrict__ W) {
    float s = 0.f;
    for (int i = blockIdx.x * 256 + threadIdx.x; i < DIM * DIM; i += 256 * 256)
        s += fabsf(W[i]);
    #pragma unroll
    for (int o = 16; o; o >>= 1) s += __shfl_xor_sync(0xFFFFFFFFu, s, o);
    __shared__ float red[8];
    if ((threadIdx.x & 31) == 0) red[threadIdx.x >> 5] = s;
    __syncthreads();
    if (threadIdx.x == 0) {
        float t = 0.f;
        #pragma unroll
        for (int w = 0; w < 8; w++) t += red[w];
        g_wpart[blockIdx.x] = t;
    }
}

__global__ void k_wabs_fin() {
    float s = g_wpart[threadIdx.x];
    #pragma unroll
    for (int o = 16; o; o >>= 1) s += __shfl_xor_sync(0xFFFFFFFFu, s, o);
    __shared__ float red[8];
    if ((threadIdx.x & 31) == 0) red[threadIdx.x >> 5] = s;
    __syncthreads();
    if (threadIdx.x == 0) {
        float t = 0.f;
        #pragma unroll
        for (int w = 0; w < 8; w++) t += red[w];
        g_wscale = fmaxf(t / (float)(DIM * DIM), 1e-6f);
    }
}

// ---------------------------------------------------------------------------
// Register/shuffle FWHT over one 2048-row, 256 threads x 8 elements.
// ---------------------------------------------------------------------------
#define BFLY(a, b) { float _x = (a), _y = (b); (a) = _x + _y; (b) = _x - _y; }

static __device__ __forceinline__ void fwht_reg8(float* v) {
    BFLY(v[0], v[1]); BFLY(v[2], v[3]); BFLY(v[4], v[5]); BFLY(v[6], v[7]);
    BFLY(v[0], v[2]); BFLY(v[1], v[3]); BFLY(v[4], v[6]); BFLY(v[5], v[7]);
    BFLY(v[0], v[4]); BFLY(v[1], v[5]); BFLY(v[2], v[6]); BFLY(v[3], v[7]);
}

static __device__ __forceinline__ void fwht_shfl5(float* v, int lane) {
    #pragma unroll
    for (int b = 1; b <= 16; b <<= 1) {
        #pragma unroll
        for (int j = 0; j < 8; j++) {
            float p = __shfl_xor_sync(0xFFFFFFFFu, v[j], b);
            v[j] = (lane & b) ? (p - v[j]) : (v[j] + p);
        }
    }
}

// K1: ternarize row o of W, FWHT, write g_B1[o][d]
__global__ void __launch_bounds__(256)
k_wq_fwht(const float* __restrict__ W) {
    __shared__ float s[DIM];
    const int o = blockIdx.x, t = threadIdx.x, lane = t & 31, w = t >> 5;
    const float ws = g_wscale, th = 0.5f * ws;
    const float* wr = W + (size_t)o * DIM;
    float v[8];
    #pragma unroll
    for (int j = 0; j < 8; j++) {
        float x = wr[j * 256 + t];
        v[j] = (x > th) ? ws : ((x < -th) ? -ws : 0.f);
    }
    fwht_reg8(v);            // bits 8,9,10
    fwht_shfl5(v, lane);     // bits 0..4
    #pragma unroll
    for (int j = 0; j < 8; j++) s[j * 256 + t] = v[j];
    __syncthreads();
    #pragma unroll
    for (int j = 0; j < 8; j++) v[j] = s[w * 256 + j * 32 + lane];
    fwht_reg8(v);            // bits 5,6,7
    float* orow = g_B1 + (size_t)o * DIM;
    #pragma unroll
    for (int j = 0; j < 8; j++) orow[w * 256 + j * 32 + lane] = v[j];
}

// K2b: FWHT rows of g_B1T (FWHT over o), round to fp16, write g_BqT[d][o]
__global__ void __launch_bounds__(256)
k_fwht_rows_half() {
    __shared__ float s[DIM];
    const int d = blockIdx.x, t = threadIdx.x, lane = t & 31, w = t >> 5;
    const float* ir = g_B1T + (size_t)d * DIM;
    float v[8];
    #pragma unroll
    for (int j = 0; j < 8; j++) v[j] = ir[j * 256 + t];
    fwht_reg8(v);
    fwht_shfl5(v, lane);
    #pragma unroll
    for (int j = 0; j < 8; j++) s[j * 256 + t] = v[j];
    __syncthreads();
    #pragma unroll
    for (int j = 0; j < 8; j++) v[j] = s[w * 256 + j * 32 + lane];
    fwht_reg8(v);
    __half* orow = g_BqT + (size_t)d * DIM;
    #pragma unroll
    for (int j = 0; j < 8; j++)
        orow[w * 256 + j * 32 + lane] = __float2half_rn(v[j]);
}

// K2a: f32 tiled transpose g_B1 -> g_B1T
__global__ void __launch_bounds__(256)
k_tr32() {
    __shared__ float t[32][33];
    const int tx = threadIdx.x, ty = threadIdx.y;
    const int x = blockIdx.x * 32 + tx, y0 = blockIdx.y * 32 + ty;
    #pragma unroll
    for (int j = 0; j < 4; j++)
        t[ty + j * 8][tx] = g_B1[(size_t)(y0 + j * 8) * DIM + x];
    __syncthreads();
    const int x2 = blockIdx.y * 32 + tx, y2 = blockIdx.x * 32 + ty;
    #pragma unroll
    for (int j = 0; j < 4; j++)
        g_B1T[(size_t)(y2 + j * 8) * DIM + x2] = t[tx][ty + j * 8];
}

// K2c: f16 tiled transpose g_BqT -> g_Bq
__global__ void __launch_bounds__(256)
k_tr16() {
    __shared__ __half t[32][34];
    const int tx = threadIdx.x, ty = threadIdx.y;
    const int x = blockIdx.x * 32 + tx, y0 = blockIdx.y * 32 + ty;
    #pragma unroll
    for (int j = 0; j < 4; j++)
        t[ty + j * 8][tx] = g_BqT[(size_t)(y0 + j * 8) * DIM + x];
    __syncthreads();
    const int x2 = blockIdx.y * 32 + tx, y2 = blockIdx.x * 32 + ty;
    #pragma unroll
    for (int j = 0; j < 4; j++)
        g_Bq[(size_t)(y2 + j * 8) * DIM + x2] = t[tx][ty + j * 8];
}

// ---------------------------------------------------------------------------
// K3: LayerNorm + 4-bit symmetric quant per row (x_int exact in fp16).
// ---------------------------------------------------------------------------
__global__ void k_ln_quant(const float* __restrict__ x,
                           const float* __restrict__ gamma,
                           const float* __restrict__ beta) {
    __shared__ float red[8];
    const int row = blockIdx.x;
    const float* xr = x + (size_t)row * DIM;
    float v[8];
    float s = 0.f;
    #pragma unroll
    for (int t = 0; t < 8; t++) { v[t] = xr[threadIdx.x + t * 256]; s += v[t]; }
    s = block_sum256(s, red);
    const float mu = s * (1.f / (float)DIM);
    float sq = 0.f;
    #pragma unroll
    for (int t = 0; t < 8; t++) { float c = v[t] - mu; sq += c * c; }
    sq = block_sum256(sq, red);
    const float rstd = rsqrtf(sq * (1.f / (float)DIM) + 1e-5f);
    float mx = 0.f;
    #pragma unroll
    for (int t = 0; t < 8; t++) {
        int j = threadIdx.x + t * 256;
        float xl = (v[t] - mu) * rstd * gamma[j] + beta[j];
        v[t] = xl;
        mx = fmaxf(mx, fabsf(xl));
    }
    mx = block_max256(mx, red);
    const float xs = fmaxf(mx, 1e-6f);
    #pragma unroll
    for (int t = 0; t < 8; t++) {
        float r = rintf(v[t] * 7.0f / xs);   // round-half-even matches jnp.round
        r = fminf(fmaxf(r, -7.f), 7.f);
        g_Xq[(size_t)row * DIM + threadIdx.x + t * 256] = __float2half_rn(r);
    }
    if (threadIdx.x == 0) g_rowscale[row] = xs * (1.f / 7.f);
}

// ---------------------------------------------------------------------------
// K4: GEMM via mma.sync (HMMA fp16, fp32 accum), 2 CTAs/SM.
//   CTA 128x128, BK=64, 256 threads, 8 warps in 2x4 grid, warp tile 64x32.
//   3-stage cp.async ring + supertile rasterization.
// ---------------------------------------------------------------------------
static __device__ __forceinline__ void load_A(uint32_t base, const __half* gA,
                                              int ksrc, int tid) {
    #pragma unroll
    for (int i = 0; i < 4; i++) {
        int idx = tid + i * GTHREADS;
        int r = idx >> 3, c = idx & 7;
        uint32_t so = (uint32_t)(r * 128 + ((c ^ (r & 7)) << 4));
        cp_async16(base + so, (const char*)(gA + (size_t)r * DIM + ksrc) + c * 16);
    }
}

static __device__ __forceinline__ void load_B(uint32_t base, const __half* gB,
                                              int ksrc, int tid) {
    #pragma unroll
    for (int i = 0; i < 4; i++) {
        int idx = tid + i * GTHREADS;
        int r = idx >> 3, c = idx & 7;
        uint32_t so = (uint32_t)(r * 128 + ((c ^ (r & 7)) << 4));
        cp_async16(base + so, (const char*)(gB + (size_t)r * DIM + ksrc) + c * 16);
    }
}

__global__ void __launch_bounds__(GTHREADS, 2)
k_gemm(float* __restrict__ out) {
    extern __shared__ char smem[];
    const uint32_t sb = smem_u32(smem);
    const int tid  = threadIdx.x;
    const int lane = tid & 31;
    const int wid  = tid >> 5;            // 0..7
    const int wm   = (wid >> 2) * 64;     // warp m-offset (2 rows of warps)
    const int wn   = (wid & 3) * 32;      // warp n-offset (4 cols of warps)

    // Supertile rasterization: 16 mt x 16 nt = 256-CTA supertiles.
    // Working set per group: A 4MB + B 4MB -> L2-resident.
    const int bid = blockIdx.x;           // 0..2047 (128 mt x 16 nt)
    const int st  = bid >> 8;             // 8 supertiles
    const int r8  = bid & 255;
    const int mt  = st * 16 + (r8 & 15);
    const int nt  = r8 >> 4;
    const int mBase = mt * BM;
    const int nBase = nt * BN;

    const __half* gA = g_Xq + (size_t)mBase * DIM;
    const __half* gB = g_Bq + (size_t)nBase * DIM;

    float acc[4][4][4];
    #pragma unroll
    for (int i = 0; i < 4; i++)
        #pragma unroll
        for (int j = 0; j < 4; j++)
            #pragma unroll
            for (int q = 0; q < 4; q++) acc[i][j][q] = 0.f;

    // Prologue: stages 0,1 <- kt 0,1
    #pragma unroll
    for (int p = 0; p < NSTAGE - 1; p++) {
        load_A(sb + p * STAGE, gA, p * BK, tid);
        load_B(sb + p * STAGE + ABYTES, gB, p * BK, tid);
        asm volatile("cp.async.commit_group;" ::: "memory");
    }

    int stage = 0;
    for (int kt = 0; kt < NKT; kt++) {
        if (kt < NKT - 1) asm volatile("cp.async.wait_group 1;" ::: "memory");
        else              asm volatile("cp.async.wait_group 0;" ::: "memory");
        __syncthreads();

        const uint32_t aB = sb + stage * STAGE;
        const uint32_t bB = aB + ABYTES;

        #pragma unroll
        for (int ks = 0; ks < 4; ks++) {
            uint32_t af[4][4], bf[4][2];
            #pragma unroll
            for (int im = 0; im < 4; im++) {
                int r = wm + im * 16 + (lane & 15);
                uint32_t chunk = (uint32_t)((ks * 2 + (lane >> 4)) ^ (r & 7));
                ldmatrix_x4(af[im], aB + r * 128 + (chunk << 4));
            }
            #pragma unroll
            for (int in = 0; in < 4; in++) {
                int r = wn + in * 8 + (lane & 7);
                uint32_t chunk = (uint32_t)((ks * 2 + ((lane >> 3) & 1)) ^ (r & 7));
                ldmatrix_x2(bf[in], bB + r * 128 + (chunk << 4));
            }
            #pragma unroll
            for (int im = 0; im < 4; im++)
                #pragma unroll
                for (int in = 0; in < 4; in++)
                    mma_f16(acc[im][in], af[im], bf[in]);
        }

        if (kt + NSTAGE - 1 < NKT) {
            const int k2 = kt + NSTAGE - 1;
            int st2 = stage + NSTAGE - 1;
            if (st2 >= NSTAGE) st2 -= NSTAGE;
            const uint32_t nb = sb + st2 * STAGE;
            load_A(nb, gA, k2 * BK, tid);
            load_B(nb + ABYTES, gB, k2 * BK, tid);
            asm volatile("cp.async.commit_group;" ::: "memory");
        }
        stage = (stage + 1 == NSTAGE) ? 0 : stage + 1;
    }

    // Epilogue: d frag -> (row = lane/4 [+8], col = 2*(lane%4) [+1])
    #pragma unroll
    for (int im = 0; im < 4; im++) {
        const int r0 = mBase + wm + im * 16 + (lane >> 2);
        const int r1 = r0 + 8;
        const float s0 = g_rowscale[r0];
        const float s1 = g_rowscale[r1];
        #pragma unroll
        for (int in = 0; in < 4; in++) {
            const int col = nBase + wn + in * 8 + (lane & 3) * 2;
            float2 v0 = make_float2(acc[im][in][0] * s0, acc[im][in][1] * s0);
            float2 v1 = make_float2(acc[im][in][2] * s1, acc[im][in][3] * s1);
            *reinterpret_cast<float2*>(out + (size_t)r0 * DIM + col) = v0;
            *reinterpret_cast<float2*>(out + (size_t)r1 * DIM + col) = v1;
        }
    }
}

// ---------------------------------------------------------------------------
// Launcher
// ---------------------------------------------------------------------------
extern "C" void kernel_launch(void* const* d_in, const int* in_sizes, int n_in,
                              void* d_out, int out_size) {
    const float* x     = (const float*)d_in[0];
    const float* W     = (const float*)d_in[1];
    const float* gamma = (const float*)d_in[2];
    const float* beta  = (const float*)d_in[3];
    float* out = (float*)d_out;

    cudaFuncSetAttribute(k_gemm, cudaFuncAttributeMaxDynamicSharedMemorySize,
                         GEMM_SMEM);

    k_wabs_part<<<256, 256>>>(W);
    k_wabs_fin<<<1, 256>>>();
    k_wq_fwht<<<DIM, 256>>>(W);
    {
        dim3 tb(32, 8);
        dim3 tg(DIM / 32, DIM / 32);
        k_tr32<<<tg, tb>>>();
    }
    k_fwht_rows_half<<<DIM, 256>>>();
    {
        dim3 tb(32, 8);
        dim3 tg(DIM / 32, DIM / 32);
        k_tr16<<<tg, tb>>>();
    }
    k_ln_quant<<<NROWS, 256>>>(x, gamma, beta);

    k_gemm<<<(NROWS / BM) * (DIM / BN), GTHREADS, GEMM_SMEM>>>(out);
}